// round 3
// baseline (speedup 1.0000x reference)
#include <cuda_runtime.h>
#include <cuda_bf16.h>
#include <cstdint>

// Problem constants
#define Bq   4
#define Nq   2048
#define FIN  128
#define Hq   4
#define Dq   64
#define ALPHA 0.2f

// Scratch (allocation-free rule: __device__ globals)
__device__ float g_h[Bq * Hq * Nq * Dq];    // h laid out [b][head][n][d]  (8 MB)
__device__ float g_o[Bq * Hq * Nq * Dq];    // per-head outputs (8 MB)
__device__ float g_ei[Bq * Hq * Nq];
__device__ float g_ej[Bq * Hq * Nq];

// ---- packed f32x2 helpers (sm_103a FFMA2) ---------------------------------
__device__ __forceinline__ unsigned long long pk2(float lo, float hi) {
    unsigned long long r;
    asm("mov.b64 %0, {%1,%2};" : "=l"(r) : "f"(lo), "f"(hi));
    return r;
}
__device__ __forceinline__ void fma2(unsigned long long& d,
                                     unsigned long long a,
                                     unsigned long long b) {
    asm("fma.rn.f32x2 %0, %1, %2, %0;" : "+l"(d) : "l"(a), "l"(b));
}
__device__ __forceinline__ float2 upk(unsigned long long v) {
    float2 f;
    asm("mov.b64 {%0,%1}, %2;" : "=f"(f.x), "=f"(f.y) : "l"(v));
    return f;
}

// ---------------------------------------------------------------------------
// Kernel 1: h = x @ W, scattered to [b][head][n][d].
// 32 rows x 256 cols per block. Thread (ty,tx): rows ty*2+{0,1},
// cols o = tx*2 + c*32 (c=0..7) -> contiguous pairs => LDS.64 + FFMA2.
// ---------------------------------------------------------------------------
__global__ __launch_bounds__(256) void k_gemm(const float* __restrict__ x,
                                              const float* __restrict__ W) {
    __shared__ float Ws[32 * 256];
    __shared__ float xs[32 * 33];

    const int tid  = threadIdx.x;
    const int row0 = blockIdx.x * 32;
    const int ty   = tid >> 4;
    const int tx   = tid & 15;

    unsigned long long acc2[2][8];
#pragma unroll
    for (int r = 0; r < 2; r++)
#pragma unroll
        for (int c = 0; c < 8; c++) acc2[r][c] = 0ull;

    for (int kc = 0; kc < FIN; kc += 32) {
        __syncthreads();
        const float4* W4 = (const float4*)(W + kc * 256);
#pragma unroll
        for (int t = 0; t < 8; t++) {
            int idx = tid + 256 * t;
            ((float4*)Ws)[idx] = W4[idx];
        }
        {
            int r  = tid >> 3;
            int kq = tid & 7;
            float4 v = *(const float4*)(x + (size_t)(row0 + r) * FIN + kc + kq * 4);
            float* dst = &xs[r * 33 + kq * 4];
            dst[0] = v.x; dst[1] = v.y; dst[2] = v.z; dst[3] = v.w;
        }
        __syncthreads();
#pragma unroll
        for (int k = 0; k < 32; k++) {
            float x0 = xs[(ty * 2 + 0) * 33 + k];
            float x1 = xs[(ty * 2 + 1) * 33 + k];
            unsigned long long xp0 = pk2(x0, x0);
            unsigned long long xp1 = pk2(x1, x1);
#pragma unroll
            for (int c = 0; c < 8; c++) {
                unsigned long long wv =
                    *(const unsigned long long*)&Ws[k * 256 + tx * 2 + c * 32];
                fma2(acc2[0][c], xp0, wv);
                fma2(acc2[1][c], xp1, wv);
            }
        }
    }

    // scatter to g_h[b][head][n][d]; pairs (o,o+1) stay inside one head
#pragma unroll
    for (int r = 0; r < 2; r++) {
        int g = row0 + ty * 2 + r;
        int b = g / Nq;
        int n = g % Nq;
#pragma unroll
        for (int c = 0; c < 8; c++) {
            int o    = tx * 2 + c * 32;
            int head = o >> 6;
            int d    = o & 63;
            float2 v = upk(acc2[r][c]);
            *(float2*)&g_h[(((size_t)b * Hq + head) * Nq + n) * Dq + d] = v;
        }
    }
}

// ---------------------------------------------------------------------------
// Kernel 2: ei/ej = h . a1 / h . a2 per (b,head,n). One warp per row.
// ---------------------------------------------------------------------------
__global__ __launch_bounds__(256) void k_ev(const float* __restrict__ a) {
    int task = blockIdx.x * 8 + (threadIdx.x >> 5);
    int lane = threadIdx.x & 31;
    const float* hr = g_h + (size_t)task * Dq;
    float v0 = hr[lane], v1 = hr[lane + 32];
    float e1 = v0 * a[lane]      + v1 * a[lane + 32];
    float e2 = v0 * a[64 + lane] + v1 * a[96 + lane];
#pragma unroll
    for (int off = 16; off > 0; off >>= 1) {
        e1 += __shfl_down_sync(0xffffffffu, e1, off);
        e2 += __shfl_down_sync(0xffffffffu, e2, off);
    }
    if (lane == 0) {
        g_ei[task] = e1;
        g_ej[task] = e2;
    }
}

// ---------------------------------------------------------------------------
// Kernel 3: fused masked-softmax attention (flash-style, no max needed).
// One (b, head, 128-row tile) per block; FFMA2 in the P@V inner loop.
// ---------------------------------------------------------------------------
__global__ __launch_bounds__(256) void k_attn(const int* __restrict__ adj) {
    __shared__ float ei_s[128];
    __shared__ float ej_s[32];
    __shared__ float V_s[32 * 64];
    __shared__ float p_s[128 * 33];
    __shared__ float dn_s[128];

    const int tid  = threadIdx.x;
    const int bt   = blockIdx.x;
    const int it   = bt & 15;
    const int head = (bt >> 4) & 3;
    const int b    = bt >> 6;
    const int i0   = it * 128;
    const int bh   = b * Hq + head;

    const float* Vg      = g_h + (size_t)bh * Nq * Dq;
    const int*   adj_row = adj + ((size_t)b * Nq + i0) * Nq;

    if (tid < 128) ei_s[tid] = g_ei[bh * Nq + i0 + tid];

    const int ty = tid >> 3;
    const int tx = tid & 7;

    unsigned long long acc2[4][4];
#pragma unroll
    for (int r = 0; r < 4; r++)
#pragma unroll
        for (int c = 0; c < 4; c++) acc2[r][c] = 0ull;
    float den[4] = {0.f, 0.f, 0.f, 0.f};

    for (int j0 = 0; j0 < Nq; j0 += 32) {
        __syncthreads();
        {
            const float4* Vt = (const float4*)(Vg + (size_t)j0 * Dq);
            ((float4*)V_s)[tid]       = Vt[tid];
            ((float4*)V_s)[tid + 256] = Vt[tid + 256];
        }
        if (tid < 32) ej_s[tid] = g_ej[bh * Nq + j0 + tid];
        __syncthreads();

        // p tile: 128 x 32
#pragma unroll
        for (int t = 0; t < 16; t++) {
            int idx = tid + 256 * t;
            int i   = idx >> 5;
            int j   = idx & 31;
            int av  = adj_row[(size_t)i * Nq + j0 + j];
            float e = ei_s[i] + ej_s[j];
            e = fmaxf(e, ALPHA * e);          // leaky relu
            float p = av ? __expf(e) : 0.f;
            p_s[i * 33 + j] = p;
        }
        __syncthreads();

        // O += p * V using packed FFMA2
#pragma unroll 8
        for (int j = 0; j < 32; j++) {
            ulonglong2 v0 = *(const ulonglong2*)&V_s[j * 64 + tx * 8];
            ulonglong2 v1 = *(const ulonglong2*)&V_s[j * 64 + tx * 8 + 4];
            float p0 = p_s[(ty * 4 + 0) * 33 + j];
            float p1 = p_s[(ty * 4 + 1) * 33 + j];
            float p2 = p_s[(ty * 4 + 2) * 33 + j];
            float p3 = p_s[(ty * 4 + 3) * 33 + j];
            if (tx == 0) { den[0] += p0; den[1] += p1; den[2] += p2; den[3] += p3; }
            unsigned long long pp0 = pk2(p0, p0);
            unsigned long long pp1 = pk2(p1, p1);
            unsigned long long pp2 = pk2(p2, p2);
            unsigned long long pp3 = pk2(p3, p3);
            fma2(acc2[0][0], pp0, v0.x); fma2(acc2[0][1], pp0, v0.y);
            fma2(acc2[0][2], pp0, v1.x); fma2(acc2[0][3], pp0, v1.y);
            fma2(acc2[1][0], pp1, v0.x); fma2(acc2[1][1], pp1, v0.y);
            fma2(acc2[1][2], pp1, v1.x); fma2(acc2[1][3], pp1, v1.y);
            fma2(acc2[2][0], pp2, v0.x); fma2(acc2[2][1], pp2, v0.y);
            fma2(acc2[2][2], pp2, v1.x); fma2(acc2[2][3], pp2, v1.y);
            fma2(acc2[3][0], pp3, v0.x); fma2(acc2[3][1], pp3, v0.y);
            fma2(acc2[3][2], pp3, v1.x); fma2(acc2[3][3], pp3, v1.y);
        }
    }

    __syncthreads();
    if (tx == 0) {
#pragma unroll
        for (int r = 0; r < 4; r++) dn_s[ty * 4 + r] = den[r];
    }
    __syncthreads();

    float* og = g_o + ((size_t)bh * Nq + i0) * Dq;
#pragma unroll
    for (int r = 0; r < 4; r++) {
        float inv = 1.f / dn_s[ty * 4 + r];
        float2 e0 = upk(acc2[r][0]);
        float2 e1 = upk(acc2[r][1]);
        float2 e2 = upk(acc2[r][2]);
        float2 e3 = upk(acc2[r][3]);
        float4 w0, w1;
        w0.x = e0.x * inv; w0.y = e0.y * inv; w0.z = e1.x * inv; w0.w = e1.y * inv;
        w1.x = e2.x * inv; w1.y = e2.y * inv; w1.z = e3.x * inv; w1.w = e3.y * inv;
        *(float4*)&og[(ty * 4 + r) * Dq + tx * 8]     = w0;
        *(float4*)&og[(ty * 4 + r) * Dq + tx * 8 + 4] = w1;
    }
}

// ---------------------------------------------------------------------------
// Kernel 4: out[b][n][d] = mean over heads of g_o
// ---------------------------------------------------------------------------
__global__ __launch_bounds__(256) void k_mean(float* __restrict__ out) {
    int idx = blockIdx.x * 256 + threadIdx.x;
    if (idx >= Bq * Nq * Dq) return;
    int d = idx & 63;
    int n = (idx >> 6) & (Nq - 1);
    int b = idx >> 17;
    float s = 0.f;
#pragma unroll
    for (int h = 0; h < Hq; h++)
        s += g_o[(((size_t)b * Hq + h) * Nq + n) * Dq + d];
    out[idx] = 0.25f * s;
}

// ---------------------------------------------------------------------------
extern "C" void kernel_launch(void* const* d_in, const int* in_sizes, int n_in,
                              void* d_out, int out_size) {
    const float* x   = (const float*)d_in[0];
    const int*   adj = (const int*)  d_in[1];
    const float* W   = (const float*)d_in[2];
    const float* a   = (const float*)d_in[3];
    float*       out = (float*)d_out;

    k_gemm<<<(Bq * Nq) / 32, 256>>>(x, W);
    k_ev  <<<(Bq * Hq * Nq) / 8, 256>>>(a);
    k_attn<<<Bq * Hq * (Nq / 128), 256>>>(adj);
    k_mean<<<(Bq * Nq * Dq + 255) / 256, 256>>>(out);
}

// round 4
// speedup vs baseline: 1.2723x; 1.2723x over previous
#include <cuda_runtime.h>
#include <cuda_bf16.h>
#include <cstdint>

// Problem constants
#define Bq   4
#define Nq   2048
#define FIN  128
#define Hq   4
#define Dq   64
#define ALPHA 0.2f
#define NSPLIT 8           // j-dimension splits of k_attn
#define JCHUNK (Nq / NSPLIT)   // 256

// Scratch (allocation-free rule: __device__ globals)
__device__ float g_h[Bq * Hq * Nq * Dq];                  // [bh][n][d] (8 MB)
__device__ float g_num[NSPLIT * Bq * Hq * Nq * Dq];       // partial numerators (67 MB)
__device__ float g_den[NSPLIT * Bq * Hq * Nq];            // partial denominators
__device__ float g_ei[Bq * Hq * Nq];
__device__ float g_ej[Bq * Hq * Nq];

// ---- packed f32x2 helpers (sm_103a FFMA2) ---------------------------------
__device__ __forceinline__ unsigned long long pk2(float lo, float hi) {
    unsigned long long r;
    asm("mov.b64 %0, {%1,%2};" : "=l"(r) : "f"(lo), "f"(hi));
    return r;
}
__device__ __forceinline__ void fma2(unsigned long long& d,
                                     unsigned long long a,
                                     unsigned long long b) {
    asm("fma.rn.f32x2 %0, %1, %2, %0;" : "+l"(d) : "l"(a), "l"(b));
}
__device__ __forceinline__ float2 upk(unsigned long long v) {
    float2 f;
    asm("mov.b64 {%0,%1}, %2;" : "=f"(f.x), "=f"(f.y) : "l"(v));
    return f;
}

// ---------------------------------------------------------------------------
// Kernel 1: h = x @ W, scattered to [b][head][n][d].
// ---------------------------------------------------------------------------
__global__ __launch_bounds__(256) void k_gemm(const float* __restrict__ x,
                                              const float* __restrict__ W) {
    __shared__ float Ws[32 * 256];
    __shared__ float xs[32 * 33];

    const int tid  = threadIdx.x;
    const int row0 = blockIdx.x * 32;
    const int ty   = tid >> 4;
    const int tx   = tid & 15;

    unsigned long long acc2[2][8];
#pragma unroll
    for (int r = 0; r < 2; r++)
#pragma unroll
        for (int c = 0; c < 8; c++) acc2[r][c] = 0ull;

    for (int kc = 0; kc < FIN; kc += 32) {
        __syncthreads();
        const float4* W4 = (const float4*)(W + kc * 256);
#pragma unroll
        for (int t = 0; t < 8; t++) {
            int idx = tid + 256 * t;
            ((float4*)Ws)[idx] = W4[idx];
        }
        {
            int r  = tid >> 3;
            int kq = tid & 7;
            float4 v = *(const float4*)(x + (size_t)(row0 + r) * FIN + kc + kq * 4);
            float* dst = &xs[r * 33 + kq * 4];
            dst[0] = v.x; dst[1] = v.y; dst[2] = v.z; dst[3] = v.w;
        }
        __syncthreads();
#pragma unroll
        for (int k = 0; k < 32; k++) {
            float x0 = xs[(ty * 2 + 0) * 33 + k];
            float x1 = xs[(ty * 2 + 1) * 33 + k];
            unsigned long long xp0 = pk2(x0, x0);
            unsigned long long xp1 = pk2(x1, x1);
#pragma unroll
            for (int c = 0; c < 8; c++) {
                unsigned long long wv =
                    *(const unsigned long long*)&Ws[k * 256 + tx * 2 + c * 32];
                fma2(acc2[0][c], xp0, wv);
                fma2(acc2[1][c], xp1, wv);
            }
        }
    }

#pragma unroll
    for (int r = 0; r < 2; r++) {
        int g = row0 + ty * 2 + r;
        int b = g / Nq;
        int n = g % Nq;
#pragma unroll
        for (int c = 0; c < 8; c++) {
            int o    = tx * 2 + c * 32;
            int head = o >> 6;
            int d    = o & 63;
            float2 v = upk(acc2[r][c]);
            *(float2*)&g_h[(((size_t)b * Hq + head) * Nq + n) * Dq + d] = v;
        }
    }
}

// ---------------------------------------------------------------------------
// Kernel 2: ei/ej per (b,head,n). One warp per row.
// ---------------------------------------------------------------------------
__global__ __launch_bounds__(256) void k_ev(const float* __restrict__ a) {
    int task = blockIdx.x * 8 + (threadIdx.x >> 5);
    int lane = threadIdx.x & 31;
    const float* hr = g_h + (size_t)task * Dq;
    float v0 = hr[lane], v1 = hr[lane + 32];
    float e1 = v0 * a[lane]      + v1 * a[lane + 32];
    float e2 = v0 * a[64 + lane] + v1 * a[96 + lane];
#pragma unroll
    for (int off = 16; off > 0; off >>= 1) {
        e1 += __shfl_down_sync(0xffffffffu, e1, off);
        e2 += __shfl_down_sync(0xffffffffu, e2, off);
    }
    if (lane == 0) {
        g_ei[task] = e1;
        g_ej[task] = e2;
    }
}

// ---------------------------------------------------------------------------
// Kernel 3: attention partials. Block = (split s, b, head, 128-row i-tile);
// j stripe of 256. Writes partial numerator/denominator. 512 CTAs total.
// ---------------------------------------------------------------------------
__global__ __launch_bounds__(256) void k_attn(const int* __restrict__ adj) {
    __shared__ float ei_s[128];
    __shared__ float ej_s[32];
    __shared__ float V_s[32 * 64];
    __shared__ float p_s[128 * 33];
    __shared__ float dn_s[128];

    const int tid  = threadIdx.x;
    const int s    = blockIdx.x & (NSPLIT - 1);
    const int bt   = blockIdx.x >> 3;
    const int it   = bt & 15;
    const int head = (bt >> 4) & 3;
    const int b    = bt >> 6;
    const int i0   = it * 128;
    const int bh   = b * Hq + head;
    const int jb   = s * JCHUNK;

    const float* Vg      = g_h + (size_t)bh * Nq * Dq;
    const int*   adj_row = adj + ((size_t)b * Nq + i0) * Nq + jb;

    if (tid < 128) ei_s[tid] = g_ei[bh * Nq + i0 + tid];

    const int ty = tid >> 3;
    const int tx = tid & 7;

    unsigned long long acc2[4][4];
#pragma unroll
    for (int r = 0; r < 4; r++)
#pragma unroll
        for (int c = 0; c < 4; c++) acc2[r][c] = 0ull;
    float den[4] = {0.f, 0.f, 0.f, 0.f};

    for (int j0 = 0; j0 < JCHUNK; j0 += 32) {
        __syncthreads();
        {
            const float4* Vt = (const float4*)(Vg + (size_t)(jb + j0) * Dq);
            ((float4*)V_s)[tid]       = Vt[tid];
            ((float4*)V_s)[tid + 256] = Vt[tid + 256];
        }
        if (tid < 32) ej_s[tid] = g_ej[bh * Nq + jb + j0 + tid];
        __syncthreads();

        // p tile: 128 x 32
#pragma unroll
        for (int t = 0; t < 16; t++) {
            int idx = tid + 256 * t;
            int i   = idx >> 5;
            int j   = idx & 31;
            int av  = adj_row[(size_t)i * Nq + j0 + j];
            float e = ei_s[i] + ej_s[j];
            e = fmaxf(e, ALPHA * e);          // leaky relu
            float p = av ? __expf(e) : 0.f;
            p_s[i * 33 + j] = p;
        }
        __syncthreads();

        // O += p * V using packed FFMA2
#pragma unroll 8
        for (int j = 0; j < 32; j++) {
            ulonglong2 v0 = *(const ulonglong2*)&V_s[j * 64 + tx * 8];
            ulonglong2 v1 = *(const ulonglong2*)&V_s[j * 64 + tx * 8 + 4];
            float p0 = p_s[(ty * 4 + 0) * 33 + j];
            float p1 = p_s[(ty * 4 + 1) * 33 + j];
            float p2 = p_s[(ty * 4 + 2) * 33 + j];
            float p3 = p_s[(ty * 4 + 3) * 33 + j];
            if (tx == 0) { den[0] += p0; den[1] += p1; den[2] += p2; den[3] += p3; }
            unsigned long long pp0 = pk2(p0, p0);
            unsigned long long pp1 = pk2(p1, p1);
            unsigned long long pp2 = pk2(p2, p2);
            unsigned long long pp3 = pk2(p3, p3);
            fma2(acc2[0][0], pp0, v0.x); fma2(acc2[0][1], pp0, v0.y);
            fma2(acc2[0][2], pp0, v1.x); fma2(acc2[0][3], pp0, v1.y);
            fma2(acc2[1][0], pp1, v0.x); fma2(acc2[1][1], pp1, v0.y);
            fma2(acc2[1][2], pp1, v1.x); fma2(acc2[1][3], pp1, v1.y);
            fma2(acc2[2][0], pp2, v0.x); fma2(acc2[2][1], pp2, v0.y);
            fma2(acc2[2][2], pp2, v1.x); fma2(acc2[2][3], pp2, v1.y);
            fma2(acc2[3][0], pp3, v0.x); fma2(acc2[3][1], pp3, v0.y);
            fma2(acc2[3][2], pp3, v1.x); fma2(acc2[3][3], pp3, v1.y);
        }
    }

    __syncthreads();
    if (tx == 0) {
#pragma unroll
        for (int r = 0; r < 4; r++) dn_s[ty * 4 + r] = den[r];
    }
    __syncthreads();

    // write partials
    float* ng = g_num + (((size_t)s * Bq * Hq + bh) * Nq + i0) * Dq;
    if (tid < 128)
        g_den[((size_t)s * Bq * Hq + bh) * Nq + i0 + tid] = dn_s[tid];
#pragma unroll
    for (int r = 0; r < 4; r++) {
        float2 e0 = upk(acc2[r][0]);
        float2 e1 = upk(acc2[r][1]);
        float2 e2 = upk(acc2[r][2]);
        float2 e3 = upk(acc2[r][3]);
        float4 w0, w1;
        w0.x = e0.x; w0.y = e0.y; w0.z = e1.x; w0.w = e1.y;
        w1.x = e2.x; w1.y = e2.y; w1.z = e3.x; w1.w = e3.y;
        *(float4*)&ng[(ty * 4 + r) * Dq + tx * 8]     = w0;
        *(float4*)&ng[(ty * 4 + r) * Dq + tx * 8 + 4] = w1;
    }
}

// ---------------------------------------------------------------------------
// Kernel 4: combine partials over splits, divide, mean over heads.
// ---------------------------------------------------------------------------
__global__ __launch_bounds__(256) void k_comb(float* __restrict__ out) {
    int idx = blockIdx.x * 256 + threadIdx.x;     // over B*N*D
    if (idx >= Bq * Nq * Dq) return;
    int d = idx & 63;
    int n = (idx >> 6) & (Nq - 1);
    int b = idx >> 17;
    float res = 0.f;
#pragma unroll
    for (int h = 0; h < Hq; h++) {
        int bh = b * Hq + h;
        float num = 0.f, den = 0.f;
#pragma unroll
        for (int s = 0; s < NSPLIT; s++) {
            num += g_num[(((size_t)s * Bq * Hq + bh) * Nq + n) * Dq + d];
            den += g_den[((size_t)s * Bq * Hq + bh) * Nq + n];
        }
        res += num / den;
    }
    out[idx] = 0.25f * res;
}

// ---------------------------------------------------------------------------
extern "C" void kernel_launch(void* const* d_in, const int* in_sizes, int n_in,
                              void* d_out, int out_size) {
    const float* x   = (const float*)d_in[0];
    const int*   adj = (const int*)  d_in[1];
    const float* W   = (const float*)d_in[2];
    const float* a   = (const float*)d_in[3];
    float*       out = (float*)d_out;

    k_gemm<<<(Bq * Nq) / 32, 256>>>(x, W);
    k_ev  <<<(Bq * Hq * Nq) / 8, 256>>>(a);
    k_attn<<<Bq * Hq * (Nq / 128) * NSPLIT, 256>>>(adj);
    k_comb<<<(Bq * Nq * Dq + 255) / 256, 256>>>(out);
}